// round 1
// baseline (speedup 1.0000x reference)
#include <cuda_runtime.h>

#define BB    2
#define NWAY  5
#define KSHOT 5
#define QQ    75
#define TT    196
#define CC    384
#define SS    (KSHOT * TT)   /* 980 */

#define VQ (BB * QQ * TT)     /* 29400 query tokens */
#define VS (BB * NWAY * SS)   /* 9800 shot tokens  */

// ---- scratch (no allocation allowed; __device__ globals) ----
__device__ float g_invq[VQ];
__device__ float g_invs[VS];
__device__ float g_proto[BB * NWAY * CC];

// ---------------------------------------------------------------------------
// Zero the logits region (d_out is poisoned; main kernel uses atomicAdd).
// ---------------------------------------------------------------------------
__global__ void zero_kernel(float* out, int n) {
    int i = blockIdx.x * blockDim.x + threadIdx.x;
    if (i < n) out[i] = 0.0f;
}

// ---------------------------------------------------------------------------
// Inverse L2 norms for all query tokens and all shot tokens (warp per vector).
// ---------------------------------------------------------------------------
__global__ void norm_kernel(const float* __restrict__ fq,
                            const float* __restrict__ fs) {
    int w    = (blockIdx.x * blockDim.x + threadIdx.x) >> 5;
    int lane = threadIdx.x & 31;
    if (w >= VQ + VS) return;
    const float* p = (w < VQ) ? (fq + (size_t)w * CC)
                              : (fs + (size_t)(w - VQ) * CC);
    float s = 0.0f;
    #pragma unroll
    for (int j = 0; j < CC / 32; ++j) {
        float v = p[lane + 32 * j];
        s += v * v;
    }
    #pragma unroll
    for (int off = 16; off >= 1; off >>= 1)
        s += __shfl_xor_sync(0xffffffffu, s, off);
    float inv = 1.0f / fmaxf(sqrtf(s), 1e-8f);
    if (lane == 0) {
        if (w < VQ) g_invq[w] = inv;
        else        g_invs[w - VQ] = inv;
    }
}

// ---------------------------------------------------------------------------
// Normalized prototypes: mean over k shots, then L2-normalize (eps 1e-12).
// grid = BB*NWAY blocks, 384 threads.
// ---------------------------------------------------------------------------
__global__ void proto_kernel(const float* __restrict__ x_shot) {
    int bn = blockIdx.x;
    int c  = threadIdx.x;
    float p = 0.0f;
    #pragma unroll
    for (int k = 0; k < KSHOT; ++k)
        p += x_shot[((size_t)bn * KSHOT + k) * CC + c];
    p *= (1.0f / KSHOT);

    float v = p * p;
    #pragma unroll
    for (int off = 16; off >= 1; off >>= 1)
        v += __shfl_xor_sync(0xffffffffu, v, off);
    __shared__ float wsum[CC / 32];
    __shared__ float s_inv;
    int lane = c & 31;
    if (lane == 0) wsum[c >> 5] = v;
    __syncthreads();
    if (c < 32) {
        float t = (c < CC / 32) ? wsum[c] : 0.0f;
        #pragma unroll
        for (int off = 16; off >= 1; off >>= 1)
            t += __shfl_xor_sync(0xffffffffu, t, off);
        if (c == 0) s_inv = 1.0f / fmaxf(sqrtf(t), 1e-12f);
    }
    __syncthreads();
    g_proto[(size_t)bn * CC + c] = p * s_inv;
}

// ---------------------------------------------------------------------------
// cls_logits = 10 * cos(x_query, proto). warp per (b,q,n).
// ---------------------------------------------------------------------------
__global__ void cls_kernel(const float* __restrict__ x_query,
                           float* __restrict__ out) {
    int w    = (blockIdx.x * blockDim.x + threadIdx.x) >> 5;
    int lane = threadIdx.x & 31;
    if (w >= BB * QQ * NWAY) return;
    int bq = w / NWAY;
    int n  = w % NWAY;
    int b  = bq / QQ;
    const float* x  = x_query + (size_t)bq * CC;
    const float* pr = g_proto + (size_t)(b * NWAY + n) * CC;
    float sq = 0.0f, dot = 0.0f;
    #pragma unroll
    for (int j = 0; j < CC / 32; ++j) {
        float v  = x[lane + 32 * j];
        float pv = pr[lane + 32 * j];
        sq  += v * v;
        dot += v * pv;
    }
    #pragma unroll
    for (int off = 16; off >= 1; off >>= 1) {
        sq  += __shfl_xor_sync(0xffffffffu, sq,  off);
        dot += __shfl_xor_sync(0xffffffffu, dot, off);
    }
    if (lane == 0)
        out[w] = 10.0f * dot / fmaxf(sqrtf(sq), 1e-12f);
}

// ---------------------------------------------------------------------------
// Main fused kernel: normalized GEMM tile (32 t-rows x 128 s-cols) with
// running max over s, then mean over t via atomicAdd partials.
// grid = (7 t-tiles, NWAY, BB*QQ), 128 threads, 4x8 register tile/thread.
// ---------------------------------------------------------------------------
#define KC 32

__global__ void __launch_bounds__(128)
main_kernel(const float* __restrict__ fq_g,
            const float* __restrict__ fs_g,
            float* __restrict__ out) {
    __shared__ float As[KC][33];                       // k-major, padded
    __shared__ __align__(16) float Bs[KC][128];        // k-major, width 128

    const int tid = threadIdx.x;
    const int tx  = tid & 15;       // col group: cols 4tx..4tx+3 and 64+4tx..
    const int ty  = tid >> 4;       // row group: rows 4ty..4ty+3
    const int t0  = blockIdx.x * 32;
    const int n   = blockIdx.y;
    const int z   = blockIdx.z;     // b*QQ + q
    const int b   = z / QQ;
    const int bn  = b * NWAY + n;
    const size_t qbase = (size_t)z  * TT * CC;
    const size_t sbase = (size_t)bn * SS * CC;

    // A-load duty (fixed per thread): rows m0 and m0+16, float4 group g0
    const int m0 = tid >> 3;        // 0..15
    const int g0 = tid & 7;         // 0..7
    const int tA0 = t0 + m0;
    const int tA1 = t0 + m0 + 16;
    const float ivA0 = (tA0 < TT) ? g_invq[z * TT + tA0] : 0.0f;
    const float ivA1 = (tA1 < TT) ? g_invq[z * TT + tA1] : 0.0f;
    const float* qrow0 = fq_g + qbase + (size_t)tA0 * CC + 4 * g0;
    const float* qrow1 = fq_g + qbase + (size_t)tA1 * CC + 4 * g0;

    float rmax[4] = {-1e30f, -1e30f, -1e30f, -1e30f};

    for (int s0 = 0; s0 < SS; s0 += 128) {
        float acc[4][8];
        #pragma unroll
        for (int i = 0; i < 4; ++i)
            #pragma unroll
            for (int j = 0; j < 8; ++j) acc[i][j] = 0.0f;

        const int   sg   = s0 + tid;                 // this thread's B row
        const float ivb  = (sg < SS) ? g_invs[bn * SS + sg] : 0.0f;
        const float* fsrow = fs_g + sbase + (size_t)sg * CC;

        for (int kc = 0; kc < CC; kc += KC) {
            __syncthreads();   // previous tile's compute done
            // ---- load A tile (2 rows x 4 floats per thread) ----
            {
                float4 a0 = make_float4(0, 0, 0, 0);
                float4 a1 = make_float4(0, 0, 0, 0);
                if (tA0 < TT) a0 = *reinterpret_cast<const float4*>(qrow0 + kc);
                if (tA1 < TT) a1 = *reinterpret_cast<const float4*>(qrow1 + kc);
                As[4 * g0 + 0][m0]      = a0.x * ivA0;
                As[4 * g0 + 1][m0]      = a0.y * ivA0;
                As[4 * g0 + 2][m0]      = a0.z * ivA0;
                As[4 * g0 + 3][m0]      = a0.w * ivA0;
                As[4 * g0 + 0][m0 + 16] = a1.x * ivA1;
                As[4 * g0 + 1][m0 + 16] = a1.y * ivA1;
                As[4 * g0 + 2][m0 + 16] = a1.z * ivA1;
                As[4 * g0 + 3][m0 + 16] = a1.w * ivA1;
            }
            // ---- load B tile (one row, 8 float4s per thread) ----
            #pragma unroll
            for (int g = 0; g < 8; ++g) {
                float4 bv = make_float4(0, 0, 0, 0);
                if (sg < SS)
                    bv = *reinterpret_cast<const float4*>(fsrow + kc + 4 * g);
                Bs[4 * g + 0][tid] = bv.x * ivb;
                Bs[4 * g + 1][tid] = bv.y * ivb;
                Bs[4 * g + 2][tid] = bv.z * ivb;
                Bs[4 * g + 3][tid] = bv.w * ivb;
            }
            __syncthreads();
            // ---- compute ----
            #pragma unroll
            for (int kk = 0; kk < KC; ++kk) {
                float a[4];
                #pragma unroll
                for (int i = 0; i < 4; ++i) a[i] = As[kk][4 * ty + i];
                float4 b0 = *reinterpret_cast<const float4*>(&Bs[kk][4 * tx]);
                float4 b1 = *reinterpret_cast<const float4*>(&Bs[kk][64 + 4 * tx]);
                #pragma unroll
                for (int i = 0; i < 4; ++i) {
                    acc[i][0] = fmaf(a[i], b0.x, acc[i][0]);
                    acc[i][1] = fmaf(a[i], b0.y, acc[i][1]);
                    acc[i][2] = fmaf(a[i], b0.z, acc[i][2]);
                    acc[i][3] = fmaf(a[i], b0.w, acc[i][3]);
                    acc[i][4] = fmaf(a[i], b1.x, acc[i][4]);
                    acc[i][5] = fmaf(a[i], b1.y, acc[i][5]);
                    acc[i][6] = fmaf(a[i], b1.z, acc[i][6]);
                    acc[i][7] = fmaf(a[i], b1.w, acc[i][7]);
                }
            }
        }
        // ---- fold this s-tile into running max (guard invalid cols) ----
        #pragma unroll
        for (int i = 0; i < 4; ++i) {
            #pragma unroll
            for (int u = 0; u < 4; ++u) {
                if (s0 + 4 * tx + u < SS)
                    rmax[i] = fmaxf(rmax[i], acc[i][u]);
                if (s0 + 64 + 4 * tx + u < SS)
                    rmax[i] = fmaxf(rmax[i], acc[i][4 + u]);
            }
        }
    }

    // ---- reduce max across the 16 tx lanes (stays within 16-lane halves) ----
    #pragma unroll
    for (int off = 8; off >= 1; off >>= 1) {
        #pragma unroll
        for (int i = 0; i < 4; ++i)
            rmax[i] = fmaxf(rmax[i], __shfl_xor_sync(0xffffffffu, rmax[i], off));
    }
    if (tx == 0) {
        float part = 0.0f;
        #pragma unroll
        for (int u = 0; u < 4; ++u)
            if (t0 + 4 * ty + u < TT) part += rmax[u];
        atomicAdd(&out[z * NWAY + n], part * (1.0f / TT));
    }
}

// ---------------------------------------------------------------------------
// Launch. Inputs (metadata order): feat_shot, feat_query, x_shot, x_query.
// Output: concat(logits [b,q,n], cls_logits [b,q,n]) -> 1500 floats.
// ---------------------------------------------------------------------------
extern "C" void kernel_launch(void* const* d_in, const int* in_sizes, int n_in,
                              void* d_out, int out_size) {
    const float* feat_shot  = (const float*)d_in[0];
    const float* feat_query = (const float*)d_in[1];
    const float* x_shot     = (const float*)d_in[2];
    const float* x_query    = (const float*)d_in[3];
    float* out = (float*)d_out;
    const int half = out_size / 2;   // 750

    zero_kernel<<<(half + 255) / 256, 256>>>(out, half);

    {   // inverse norms for all (VQ + VS) vectors, warp per vector
        int warps  = VQ + VS;
        int blocks = (warps * 32 + 255) / 256;
        norm_kernel<<<blocks, 256>>>(feat_query, feat_shot);
    }

    proto_kernel<<<BB * NWAY, CC>>>(x_shot);

    {   // cls logits, warp per (b,q,n)
        int warps  = BB * QQ * NWAY;
        int blocks = (warps * 32 + 255) / 256;
        cls_kernel<<<blocks, 256>>>(x_query, out + half);
    }

    dim3 grid((TT + 31) / 32, NWAY, BB * QQ);   // (7, 5, 150)
    main_kernel<<<grid, 128>>>(feat_query, feat_shot, out);
}

// round 2
// speedup vs baseline: 1.6406x; 1.6406x over previous
#include <cuda_runtime.h>

#define BB    2
#define NWAY  5
#define KSHOT 5
#define QQ    75
#define TT    196
#define CC    384
#define SS    (KSHOT * TT)   /* 980 */

#define VQ (BB * QQ * TT)     /* 29400 query tokens */
#define VS (BB * NWAY * SS)   /* 9800 shot tokens  */

// ---- scratch (no allocation allowed; __device__ globals) ----
__device__ float g_invq[VQ];
__device__ float g_invs[VS];
__device__ float g_proto[BB * NWAY * CC];

// ---------------------------------------------------------------------------
// Zero the logits region (d_out is poisoned; main kernel uses atomicAdd).
// ---------------------------------------------------------------------------
__global__ void zero_kernel(float* out, int n) {
    int i = blockIdx.x * blockDim.x + threadIdx.x;
    if (i < n) out[i] = 0.0f;
}

// ---------------------------------------------------------------------------
// Inverse L2 norms for all query tokens and all shot tokens (warp per vector).
// ---------------------------------------------------------------------------
__global__ void norm_kernel(const float* __restrict__ fq,
                            const float* __restrict__ fs) {
    int w    = (blockIdx.x * blockDim.x + threadIdx.x) >> 5;
    int lane = threadIdx.x & 31;
    if (w >= VQ + VS) return;
    const float* p = (w < VQ) ? (fq + (size_t)w * CC)
                              : (fs + (size_t)(w - VQ) * CC);
    float s = 0.0f;
    #pragma unroll
    for (int j = 0; j < CC / 32; ++j) {
        float v = p[lane + 32 * j];
        s += v * v;
    }
    #pragma unroll
    for (int off = 16; off >= 1; off >>= 1)
        s += __shfl_xor_sync(0xffffffffu, s, off);
    float inv = 1.0f / fmaxf(sqrtf(s), 1e-8f);
    if (lane == 0) {
        if (w < VQ) g_invq[w] = inv;
        else        g_invs[w - VQ] = inv;
    }
}

// ---------------------------------------------------------------------------
// Normalized prototypes: mean over k shots, then L2-normalize (eps 1e-12).
// grid = BB*NWAY blocks, 384 threads.
// ---------------------------------------------------------------------------
__global__ void proto_kernel(const float* __restrict__ x_shot) {
    int bn = blockIdx.x;
    int c  = threadIdx.x;
    float p = 0.0f;
    #pragma unroll
    for (int k = 0; k < KSHOT; ++k)
        p += x_shot[((size_t)bn * KSHOT + k) * CC + c];
    p *= (1.0f / KSHOT);

    float v = p * p;
    #pragma unroll
    for (int off = 16; off >= 1; off >>= 1)
        v += __shfl_xor_sync(0xffffffffu, v, off);
    __shared__ float wsum[CC / 32];
    __shared__ float s_inv;
    int lane = c & 31;
    if (lane == 0) wsum[c >> 5] = v;
    __syncthreads();
    if (c < 32) {
        float t = (c < CC / 32) ? wsum[c] : 0.0f;
        #pragma unroll
        for (int off = 16; off >= 1; off >>= 1)
            t += __shfl_xor_sync(0xffffffffu, t, off);
        if (c == 0) s_inv = 1.0f / fmaxf(sqrtf(t), 1e-12f);
    }
    __syncthreads();
    g_proto[(size_t)bn * CC + c] = p * s_inv;
}

// ---------------------------------------------------------------------------
// cls_logits = 10 * cos(x_query, proto). warp per (b,q,n).
// ---------------------------------------------------------------------------
__global__ void cls_kernel(const float* __restrict__ x_query,
                           float* __restrict__ out) {
    int w    = (blockIdx.x * blockDim.x + threadIdx.x) >> 5;
    int lane = threadIdx.x & 31;
    if (w >= BB * QQ * NWAY) return;
    int bq = w / NWAY;
    int n  = w % NWAY;
    int b  = bq / QQ;
    const float* x  = x_query + (size_t)bq * CC;
    const float* pr = g_proto + (size_t)(b * NWAY + n) * CC;
    float sq = 0.0f, dot = 0.0f;
    #pragma unroll
    for (int j = 0; j < CC / 32; ++j) {
        float v  = x[lane + 32 * j];
        float pv = pr[lane + 32 * j];
        sq  += v * v;
        dot += v * pv;
    }
    #pragma unroll
    for (int off = 16; off >= 1; off >>= 1) {
        sq  += __shfl_xor_sync(0xffffffffu, sq,  off);
        dot += __shfl_xor_sync(0xffffffffu, dot, off);
    }
    if (lane == 0)
        out[w] = 10.0f * dot / fmaxf(sqrtf(sq), 1e-12f);
}

// ---------------------------------------------------------------------------
// Main fused kernel: normalized GEMM tile (32 t-rows x 128 s-cols) with
// running max over s, then mean over t via atomicAdd partials.
// grid = (7 t-tiles, NWAY, BB*QQ), 128 threads, 4x8 register tile/thread.
// ---------------------------------------------------------------------------
#define KC 32

__global__ void __launch_bounds__(128)
main_kernel(const float* __restrict__ fq_g,
            const float* __restrict__ fs_g,
            float* __restrict__ out) {
    __shared__ float As[KC][33];                       // k-major, padded
    __shared__ __align__(16) float Bs[KC][128];        // k-major, width 128

    const int tid = threadIdx.x;
    const int tx  = tid & 15;       // col group: cols 4tx..4tx+3 and 64+4tx..
    const int ty  = tid >> 4;       // row group: rows 4ty..4ty+3
    const int t0  = blockIdx.x * 32;
    const int n   = blockIdx.y;
    const int z   = blockIdx.z;     // b*QQ + q
    const int b   = z / QQ;
    const int bn  = b * NWAY + n;
    const size_t qbase = (size_t)z  * TT * CC;
    const size_t sbase = (size_t)bn * SS * CC;

    // A-load duty (fixed per thread): rows m0 and m0+16, float4 group g0
    const int m0 = tid >> 3;        // 0..15
    const int g0 = tid & 7;         // 0..7
    const int tA0 = t0 + m0;
    const int tA1 = t0 + m0 + 16;
    const float ivA0 = (tA0 < TT) ? g_invq[z * TT + tA0] : 0.0f;
    const float ivA1 = (tA1 < TT) ? g_invq[z * TT + tA1] : 0.0f;
    const float* qrow0 = fq_g + qbase + (size_t)tA0 * CC + 4 * g0;
    const float* qrow1 = fq_g + qbase + (size_t)tA1 * CC + 4 * g0;

    float rmax[4] = {-1e30f, -1e30f, -1e30f, -1e30f};

    for (int s0 = 0; s0 < SS; s0 += 128) {
        float acc[4][8];
        #pragma unroll
        for (int i = 0; i < 4; ++i)
            #pragma unroll
            for (int j = 0; j < 8; ++j) acc[i][j] = 0.0f;

        const int   sg   = s0 + tid;                 // this thread's B row
        const float ivb  = (sg < SS) ? g_invs[bn * SS + sg] : 0.0f;
        const float* fsrow = fs_g + sbase + (size_t)sg * CC;

        for (int kc = 0; kc < CC; kc += KC) {
            __syncthreads();   // previous tile's compute done
            // ---- load A tile (2 rows x 4 floats per thread) ----
            {
                float4 a0 = make_float4(0, 0, 0, 0);
                float4 a1 = make_float4(0, 0, 0, 0);
                if (tA0 < TT) a0 = *reinterpret_cast<const float4*>(qrow0 + kc);
                if (tA1 < TT) a1 = *reinterpret_cast<const float4*>(qrow1 + kc);
                As[4 * g0 + 0][m0]      = a0.x * ivA0;
                As[4 * g0 + 1][m0]      = a0.y * ivA0;
                As[4 * g0 + 2][m0]      = a0.z * ivA0;
                As[4 * g0 + 3][m0]      = a0.w * ivA0;
                As[4 * g0 + 0][m0 + 16] = a1.x * ivA1;
                As[4 * g0 + 1][m0 + 16] = a1.y * ivA1;
                As[4 * g0 + 2][m0 + 16] = a1.z * ivA1;
                As[4 * g0 + 3][m0 + 16] = a1.w * ivA1;
            }
            // ---- load B tile (one row, 8 float4s per thread) ----
            #pragma unroll
            for (int g = 0; g < 8; ++g) {
                float4 bv = make_float4(0, 0, 0, 0);
                if (sg < SS)
                    bv = *reinterpret_cast<const float4*>(fsrow + kc + 4 * g);
                Bs[4 * g + 0][tid] = bv.x * ivb;
                Bs[4 * g + 1][tid] = bv.y * ivb;
                Bs[4 * g + 2][tid] = bv.z * ivb;
                Bs[4 * g + 3][tid] = bv.w * ivb;
            }
            __syncthreads();
            // ---- compute ----
            #pragma unroll
            for (int kk = 0; kk < KC; ++kk) {
                float a[4];
                #pragma unroll
                for (int i = 0; i < 4; ++i) a[i] = As[kk][4 * ty + i];
                float4 b0 = *reinterpret_cast<const float4*>(&Bs[kk][4 * tx]);
                float4 b1 = *reinterpret_cast<const float4*>(&Bs[kk][64 + 4 * tx]);
                #pragma unroll
                for (int i = 0; i < 4; ++i) {
                    acc[i][0] = fmaf(a[i], b0.x, acc[i][0]);
                    acc[i][1] = fmaf(a[i], b0.y, acc[i][1]);
                    acc[i][2] = fmaf(a[i], b0.z, acc[i][2]);
                    acc[i][3] = fmaf(a[i], b0.w, acc[i][3]);
                    acc[i][4] = fmaf(a[i], b1.x, acc[i][4]);
                    acc[i][5] = fmaf(a[i], b1.y, acc[i][5]);
                    acc[i][6] = fmaf(a[i], b1.z, acc[i][6]);
                    acc[i][7] = fmaf(a[i], b1.w, acc[i][7]);
                }
            }
        }
        // ---- fold this s-tile into running max (guard invalid cols) ----
        #pragma unroll
        for (int i = 0; i < 4; ++i) {
            #pragma unroll
            for (int u = 0; u < 4; ++u) {
                if (s0 + 4 * tx + u < SS)
                    rmax[i] = fmaxf(rmax[i], acc[i][u]);
                if (s0 + 64 + 4 * tx + u < SS)
                    rmax[i] = fmaxf(rmax[i], acc[i][4 + u]);
            }
        }
    }

    // ---- reduce max across the 16 tx lanes (stays within 16-lane halves) ----
    #pragma unroll
    for (int off = 8; off >= 1; off >>= 1) {
        #pragma unroll
        for (int i = 0; i < 4; ++i)
            rmax[i] = fmaxf(rmax[i], __shfl_xor_sync(0xffffffffu, rmax[i], off));
    }
    if (tx == 0) {
        float part = 0.0f;
        #pragma unroll
        for (int u = 0; u < 4; ++u)
            if (t0 + 4 * ty + u < TT) part += rmax[u];
        atomicAdd(&out[z * NWAY + n], part * (1.0f / TT));
    }
}

// ---------------------------------------------------------------------------
// Launch. Inputs (metadata order): feat_shot, feat_query, x_shot, x_query.
// Output: concat(logits [b,q,n], cls_logits [b,q,n]) -> 1500 floats.
// ---------------------------------------------------------------------------
extern "C" void kernel_launch(void* const* d_in, const int* in_sizes, int n_in,
                              void* d_out, int out_size) {
    const float* feat_shot  = (const float*)d_in[0];
    const float* feat_query = (const float*)d_in[1];
    const float* x_shot     = (const float*)d_in[2];
    const float* x_query    = (const float*)d_in[3];
    float* out = (float*)d_out;
    const int half = out_size / 2;   // 750

    zero_kernel<<<(half + 255) / 256, 256>>>(out, half);

    {   // inverse norms for all (VQ + VS) vectors, warp per vector
        int warps  = VQ + VS;
        int blocks = (warps * 32 + 255) / 256;
        norm_kernel<<<blocks, 256>>>(feat_query, feat_shot);
    }

    proto_kernel<<<BB * NWAY, CC>>>(x_shot);

    {   // cls logits, warp per (b,q,n)
        int warps  = BB * QQ * NWAY;
        int blocks = (warps * 32 + 255) / 256;
        cls_kernel<<<blocks, 256>>>(x_query, out + half);
    }

    dim3 grid((TT + 31) / 32, NWAY, BB * QQ);   // (7, 5, 150)
    main_kernel<<<grid, 128>>>(feat_query, feat_shot, out);
}

// round 3
// speedup vs baseline: 20.3930x; 12.4298x over previous
#include <cuda_runtime.h>
#include <cuda_bf16.h>
#include <cstdint>

#define BB    2
#define NWAY  5
#define KSHOT 5
#define QQ    75
#define TT    196
#define CC    384
#define SS    (KSHOT * TT)      /* 980 */
#define MROWS (QQ * TT)         /* 14700 rows per batch */

#define VQ (BB * QQ * TT)       /* 29400 query tokens */
#define VS (BB * NWAY * SS)     /* 9800 shot tokens  */

// ---- scratch (__device__ globals; no allocation allowed) ----
__device__ __align__(16) __nv_bfloat16 g_fqb[(size_t)VQ * CC];  // normalized bf16 queries
__device__ __align__(16) __nv_bfloat16 g_fsb[(size_t)VS * CC];  // normalized bf16 shots
__device__ float g_proto[BB * NWAY * CC];

// ---------------------------------------------------------------------------
// Zero the logits region (d_out poisoned; main kernel accumulates with atomics)
// ---------------------------------------------------------------------------
__global__ void zero_kernel(float* out, int n) {
    int i = blockIdx.x * blockDim.x + threadIdx.x;
    if (i < n) out[i] = 0.0f;
}

// ---------------------------------------------------------------------------
// Fused L2-normalize (fp32) + bf16 convert. Warp per vector.
// ---------------------------------------------------------------------------
__global__ void convert_kernel(const float* __restrict__ fq,
                               const float* __restrict__ fs) {
    int w    = (blockIdx.x * blockDim.x + threadIdx.x) >> 5;
    int lane = threadIdx.x & 31;
    if (w >= VQ + VS) return;
    const float* p;
    __nv_bfloat16* o;
    if (w < VQ) { p = fq + (size_t)w * CC;        o = g_fqb + (size_t)w * CC; }
    else        { p = fs + (size_t)(w - VQ) * CC; o = g_fsb + (size_t)(w - VQ) * CC; }
    float v[CC / 32];
    float s = 0.0f;
    #pragma unroll
    for (int j = 0; j < CC / 32; ++j) {
        v[j] = p[lane + 32 * j];
        s += v[j] * v[j];
    }
    #pragma unroll
    for (int off = 16; off >= 1; off >>= 1)
        s += __shfl_xor_sync(0xffffffffu, s, off);
    float inv = 1.0f / fmaxf(sqrtf(s), 1e-8f);
    #pragma unroll
    for (int j = 0; j < CC / 32; ++j)
        o[lane + 32 * j] = __float2bfloat16(v[j] * inv);
}

// ---------------------------------------------------------------------------
// Prototypes (fp32, tiny).
// ---------------------------------------------------------------------------
__global__ void proto_kernel(const float* __restrict__ x_shot) {
    int bn = blockIdx.x;
    int c  = threadIdx.x;
    float p = 0.0f;
    #pragma unroll
    for (int k = 0; k < KSHOT; ++k)
        p += x_shot[((size_t)bn * KSHOT + k) * CC + c];
    p *= (1.0f / KSHOT);
    float v = p * p;
    #pragma unroll
    for (int off = 16; off >= 1; off >>= 1)
        v += __shfl_xor_sync(0xffffffffu, v, off);
    __shared__ float wsum[CC / 32];
    __shared__ float s_inv;
    int lane = c & 31;
    if (lane == 0) wsum[c >> 5] = v;
    __syncthreads();
    if (c < 32) {
        float t = (c < CC / 32) ? wsum[c] : 0.0f;
        #pragma unroll
        for (int off = 16; off >= 1; off >>= 1)
            t += __shfl_xor_sync(0xffffffffu, t, off);
        if (c == 0) s_inv = 1.0f / fmaxf(sqrtf(t), 1e-12f);
    }
    __syncthreads();
    g_proto[(size_t)bn * CC + c] = p * s_inv;
}

__global__ void cls_kernel(const float* __restrict__ x_query,
                           float* __restrict__ out) {
    int w    = (blockIdx.x * blockDim.x + threadIdx.x) >> 5;
    int lane = threadIdx.x & 31;
    if (w >= BB * QQ * NWAY) return;
    int bq = w / NWAY;
    int n  = w % NWAY;
    int b  = bq / QQ;
    const float* x  = x_query + (size_t)bq * CC;
    const float* pr = g_proto + (size_t)(b * NWAY + n) * CC;
    float sq = 0.0f, dot = 0.0f;
    #pragma unroll
    for (int j = 0; j < CC / 32; ++j) {
        float v  = x[lane + 32 * j];
        float pv = pr[lane + 32 * j];
        sq  += v * v;
        dot += v * pv;
    }
    #pragma unroll
    for (int off = 16; off >= 1; off >>= 1) {
        sq  += __shfl_xor_sync(0xffffffffu, sq,  off);
        dot += __shfl_xor_sync(0xffffffffu, dot, off);
    }
    if (lane == 0)
        out[w] = 10.0f * dot / fmaxf(sqrtf(sq), 1e-12f);
}

// ---------------------------------------------------------------------------
// Main: bf16 tensor-core GEMM 128 x 980 x 384 per block with fused max+mean.
// grid = (115 m-tiles, NWAY, BB); 256 threads = 8 warps (2 m x 4 n).
// Warp tile 64x32: 4 m-frags x 4 n-frags of m16n8k16.
// ---------------------------------------------------------------------------
#define MT   128
#define KPAD 72   /* 64 bf16 + 8 pad -> 144B rows, conflict-free ldmatrix */

__device__ __forceinline__ void ldsm_x4(uint32_t& r0, uint32_t& r1,
                                        uint32_t& r2, uint32_t& r3,
                                        uint32_t addr) {
    asm volatile("ldmatrix.sync.aligned.m8n8.x4.shared.b16 {%0,%1,%2,%3}, [%4];"
                 : "=r"(r0), "=r"(r1), "=r"(r2), "=r"(r3) : "r"(addr));
}

__device__ __forceinline__ void mma_bf16(float& d0, float& d1, float& d2, float& d3,
                                         uint32_t a0, uint32_t a1, uint32_t a2, uint32_t a3,
                                         uint32_t b0, uint32_t b1) {
    asm volatile("mma.sync.aligned.m16n8k16.row.col.f32.bf16.bf16.f32 "
                 "{%0,%1,%2,%3}, {%4,%5,%6,%7}, {%8,%9}, {%0,%1,%2,%3};"
                 : "+f"(d0), "+f"(d1), "+f"(d2), "+f"(d3)
                 : "r"(a0), "r"(a1), "r"(a2), "r"(a3), "r"(b0), "r"(b1));
}

__global__ void __launch_bounds__(256)
mma_main_kernel(float* __restrict__ out) {
    __shared__ __align__(16) __nv_bfloat16 As[MT][KPAD];
    __shared__ __align__(16) __nv_bfloat16 Bs[MT][KPAD];
    __shared__ float red[MT][4];

    const int tid  = threadIdx.x;
    const int warp = tid >> 5;
    const int lane = tid & 31;
    const int wy   = warp >> 2;        // 0..1  (m strip of 64)
    const int wx   = warp & 3;         // 0..3  (n strip of 32)
    const int gid  = lane >> 2;
    const int tig  = lane & 3;
    const int n     = blockIdx.y;
    const int b     = blockIdx.z;
    const int mrow0 = blockIdx.x * MT;

    const __nv_bfloat16* aG = g_fqb + (size_t)b * MROWS * CC;
    const __nv_bfloat16* bG = g_fsb + (size_t)(b * NWAY + n) * SS * CC;

    // smem fill duty: 16B per thread, 32 rows per sweep
    const int seg = tid & 7;
    const int rb  = tid >> 3;

    // ldmatrix per-thread address bases
    const uint32_t sA = (uint32_t)__cvta_generic_to_shared(&As[0][0]);
    const uint32_t sB = (uint32_t)__cvta_generic_to_shared(&Bs[0][0]);
    const int aRow = wy * 64 + (lane & 15);
    const int aCol = (lane >> 4) * 8;
    const int bRow = wx * 32 + (lane & 7) + ((lane >> 4) << 3);
    const int bCol = ((lane >> 3) & 1) * 8;

    float rmax[4][2];
    #pragma unroll
    for (int i = 0; i < 4; ++i) { rmax[i][0] = -1e30f; rmax[i][1] = -1e30f; }

    for (int nt = 0; nt < 8; ++nt) {           // 8 tiles cover 980 s-cols
        float acc[4][4][4];
        #pragma unroll
        for (int i = 0; i < 4; ++i)
            #pragma unroll
            for (int j = 0; j < 4; ++j)
                #pragma unroll
                for (int r = 0; r < 4; ++r) acc[i][j][r] = 0.0f;

        for (int kc = 0; kc < CC; kc += 64) {
            __syncthreads();
            #pragma unroll
            for (int it = 0; it < 4; ++it) {
                int r  = rb + 32 * it;
                int gr = mrow0 + r;
                uint4 va = make_uint4(0u, 0u, 0u, 0u);
                if (gr < MROWS)
                    va = *reinterpret_cast<const uint4*>(aG + (size_t)gr * CC + kc + 8 * seg);
                *reinterpret_cast<uint4*>(&As[r][8 * seg]) = va;
                int s = nt * 128 + r;
                uint4 vb = make_uint4(0u, 0u, 0u, 0u);
                if (s < SS)
                    vb = *reinterpret_cast<const uint4*>(bG + (size_t)s * CC + kc + 8 * seg);
                *reinterpret_cast<uint4*>(&Bs[r][8 * seg]) = vb;
            }
            __syncthreads();

            #pragma unroll
            for (int ks = 0; ks < 4; ++ks) {   // 4 x k16 within the 64-chunk
                uint32_t a[4][4];
                #pragma unroll
                for (int i = 0; i < 4; ++i) {
                    uint32_t addr = sA + (uint32_t)(((aRow + i * 16) * KPAD + ks * 16 + aCol) * 2);
                    ldsm_x4(a[i][0], a[i][1], a[i][2], a[i][3], addr);
                }
                uint32_t bf[4][2];
                #pragma unroll
                for (int jp = 0; jp < 2; ++jp) {
                    uint32_t addr = sB + (uint32_t)(((bRow + jp * 16) * KPAD + ks * 16 + bCol) * 2);
                    uint32_t r0, r1, r2, r3;
                    ldsm_x4(r0, r1, r2, r3, addr);
                    bf[2 * jp][0] = r0; bf[2 * jp][1] = r1;
                    bf[2 * jp + 1][0] = r2; bf[2 * jp + 1][1] = r3;
                }
                #pragma unroll
                for (int i = 0; i < 4; ++i)
                    #pragma unroll
                    for (int j = 0; j < 4; ++j)
                        mma_bf16(acc[i][j][0], acc[i][j][1], acc[i][j][2], acc[i][j][3],
                                 a[i][0], a[i][1], a[i][2], a[i][3],
                                 bf[j][0], bf[j][1]);
            }
        }

        // fold this s-tile into running per-row max (guard padded cols)
        #pragma unroll
        for (int i = 0; i < 4; ++i)
            #pragma unroll
            for (int j = 0; j < 4; ++j)
                #pragma unroll
                for (int r = 0; r < 4; ++r) {
                    int col = nt * 128 + wx * 32 + j * 8 + 2 * tig + (r & 1);
                    if (col < SS)
                        rmax[i][r >> 1] = fmaxf(rmax[i][r >> 1], acc[i][j][r]);
                }
    }

    // reduce over the 4 lanes sharing each row (tig axis)
    #pragma unroll
    for (int i = 0; i < 4; ++i)
        #pragma unroll
        for (int h = 0; h < 2; ++h) {
            float v = rmax[i][h];
            v = fmaxf(v, __shfl_xor_sync(0xffffffffu, v, 1));
            v = fmaxf(v, __shfl_xor_sync(0xffffffffu, v, 2));
            rmax[i][h] = v;
        }
    if (tig == 0) {
        #pragma unroll
        for (int i = 0; i < 4; ++i)
            #pragma unroll
            for (int h = 0; h < 2; ++h)
                red[wy * 64 + i * 16 + h * 8 + gid][wx] = rmax[i][h];
    }
    __syncthreads();

    if (tid < MT) {
        float m = fmaxf(fmaxf(red[tid][0], red[tid][1]),
                        fmaxf(red[tid][2], red[tid][3]));
        int gr = mrow0 + tid;
        if (gr < MROWS) {
            int q = gr / TT;
            atomicAdd(&out[(b * QQ + q) * NWAY + n], m * (1.0f / TT));
        }
    }
}

// ---------------------------------------------------------------------------
// Launch. Inputs: feat_shot, feat_query, x_shot, x_query. Output: 1500 floats.
// ---------------------------------------------------------------------------
extern "C" void kernel_launch(void* const* d_in, const int* in_sizes, int n_in,
                              void* d_out, int out_size) {
    const float* feat_shot  = (const float*)d_in[0];
    const float* feat_query = (const float*)d_in[1];
    const float* x_shot     = (const float*)d_in[2];
    const float* x_query    = (const float*)d_in[3];
    float* out = (float*)d_out;
    const int half = out_size / 2;   // 750

    zero_kernel<<<(half + 255) / 256, 256>>>(out, half);

    {   // normalize + bf16 convert, warp per vector
        int warps  = VQ + VS;
        int blocks = (warps * 32 + 255) / 256;
        convert_kernel<<<blocks, 256>>>(feat_query, feat_shot);
    }

    proto_kernel<<<BB * NWAY, CC>>>(x_shot);

    {   // cls logits
        int warps  = BB * QQ * NWAY;
        int blocks = (warps * 32 + 255) / 256;
        cls_kernel<<<blocks, 256>>>(x_query, out + half);
    }

    dim3 grid((MROWS + MT - 1) / MT, NWAY, BB);   // (115, 5, 2)
    mma_main_kernel<<<grid, 256>>>(out);
}

// round 6
// speedup vs baseline: 24.4960x; 1.2012x over previous
#include <cuda_runtime.h>
#include <cuda_bf16.h>
#include <cstdint>

#define BB    2
#define NWAY  5
#define KSHOT 5
#define QQ    75
#define TT    196
#define CC    384
#define SS    (KSHOT * TT)      /* 980 */
#define MROWS (QQ * TT)         /* 14700 rows per batch */

#define VQ (BB * QQ * TT)       /* 29400 query tokens */
#define VS (BB * NWAY * SS)     /* 9800 shot tokens  */

// Tiling: CTA = 256 m-rows x full K resident, streams 8 s-tiles of 128.
#define MC      256
#define NTILE   128
#define NST     8               /* s-tiles */
#define KCH     64              /* bf16 per k-chunk = 128B rows */
#define NCH     6               /* k-chunks */
#define NCHUNKS (NST * NCH)     /* 48 B-chunk loads */
#define ACHUNK_BYTES 32768      /* 256 rows x 128B */
#define BCHUNK_BYTES 16384      /* 128 rows x 128B */
#define A_BYTES (NCH * ACHUNK_BYTES)          /* 196608 */
#define B_OFFSET A_BYTES
#define DSMEM_BYTES (A_BYTES + 2 * BCHUNK_BYTES)  /* 229376 */

// ---- scratch (__device__ globals; no allocation allowed) ----
__device__ __align__(16) __nv_bfloat16 g_fqb[(size_t)VQ * CC];
__device__ __align__(16) __nv_bfloat16 g_fsb[(size_t)VS * CC];
__device__ float g_proto[BB * NWAY * CC];

// ===========================================================================
// helpers
// ===========================================================================
__device__ __forceinline__ void ldsm_x4(uint32_t& r0, uint32_t& r1,
                                        uint32_t& r2, uint32_t& r3,
                                        uint32_t addr) {
    asm volatile("ldmatrix.sync.aligned.m8n8.x4.shared.b16 {%0,%1,%2,%3}, [%4];"
                 : "=r"(r0), "=r"(r1), "=r"(r2), "=r"(r3) : "r"(addr));
}

__device__ __forceinline__ void mma_bf16(float& d0, float& d1, float& d2, float& d3,
                                         uint32_t a0, uint32_t a1, uint32_t a2, uint32_t a3,
                                         uint32_t b0, uint32_t b1) {
    asm volatile("mma.sync.aligned.m16n8k16.row.col.f32.bf16.bf16.f32 "
                 "{%0,%1,%2,%3}, {%4,%5,%6,%7}, {%8,%9}, {%0,%1,%2,%3};"
                 : "+f"(d0), "+f"(d1), "+f"(d2), "+f"(d3)
                 : "r"(a0), "r"(a1), "r"(a2), "r"(a3), "r"(b0), "r"(b1));
}

__device__ __forceinline__ void cp16(uint32_t dst, const void* src, int sz) {
    asm volatile("cp.async.cg.shared.global [%0], [%1], 16, %2;"
                 :: "r"(dst), "l"(src), "r"(sz) : "memory");
}

#define CP_COMMIT() asm volatile("cp.async.commit_group;" ::: "memory")
#define CP_WAIT1()  asm volatile("cp.async.wait_group 1;"  ::: "memory")
#define CP_WAIT0()  asm volatile("cp.async.wait_group 0;"  ::: "memory")

__device__ __forceinline__ uint32_t sw128(uint32_t off) {
    return off ^ ((off >> 3) & 0x70);
}

// ===========================================================================
// small kernels (unchanged)
// ===========================================================================
__global__ void zero_kernel(float* out, int n) {
    int i = blockIdx.x * blockDim.x + threadIdx.x;
    if (i < n) out[i] = 0.0f;
}

__global__ void convert_kernel(const float* __restrict__ fq,
                               const float* __restrict__ fs) {
    int w    = (blockIdx.x * blockDim.x + threadIdx.x) >> 5;
    int lane = threadIdx.x & 31;
    if (w >= VQ + VS) return;
    const float* p;
    __nv_bfloat16* o;
    if (w < VQ) { p = fq + (size_t)w * CC;        o = g_fqb + (size_t)w * CC; }
    else        { p = fs + (size_t)(w - VQ) * CC; o = g_fsb + (size_t)(w - VQ) * CC; }
    float v[CC / 32];
    float s = 0.0f;
    #pragma unroll
    for (int j = 0; j < CC / 32; ++j) {
        v[j] = p[lane + 32 * j];
        s += v[j] * v[j];
    }
    #pragma unroll
    for (int off = 16; off >= 1; off >>= 1)
        s += __shfl_xor_sync(0xffffffffu, s, off);
    float inv = 1.0f / fmaxf(sqrtf(s), 1e-8f);
    #pragma unroll
    for (int j = 0; j < CC / 32; ++j)
        o[lane + 32 * j] = __float2bfloat16(v[j] * inv);
}

__global__ void proto_kernel(const float* __restrict__ x_shot) {
    int bn = blockIdx.x;
    int c  = threadIdx.x;
    float p = 0.0f;
    #pragma unroll
    for (int k = 0; k < KSHOT; ++k)
        p += x_shot[((size_t)bn * KSHOT + k) * CC + c];
    p *= (1.0f / KSHOT);
    float v = p * p;
    #pragma unroll
    for (int off = 16; off >= 1; off >>= 1)
        v += __shfl_xor_sync(0xffffffffu, v, off);
    __shared__ float wsum[CC / 32];
    __shared__ float s_inv;
    int lane = c & 31;
    if (lane == 0) wsum[c >> 5] = v;
    __syncthreads();
    if (c < 32) {
        float t = (c < CC / 32) ? wsum[c] : 0.0f;
        #pragma unroll
        for (int off = 16; off >= 1; off >>= 1)
            t += __shfl_xor_sync(0xffffffffu, t, off);
        if (c == 0) s_inv = 1.0f / fmaxf(sqrtf(t), 1e-12f);
    }
    __syncthreads();
    g_proto[(size_t)bn * CC + c] = p * s_inv;
}

__global__ void cls_kernel(const float* __restrict__ x_query,
                           float* __restrict__ out) {
    int w    = (blockIdx.x * blockDim.x + threadIdx.x) >> 5;
    int lane = threadIdx.x & 31;
    if (w >= BB * QQ * NWAY) return;
    int bq = w / NWAY;
    int n  = w % NWAY;
    int b  = bq / QQ;
    const float* x  = x_query + (size_t)bq * CC;
    const float* pr = g_proto + (size_t)(b * NWAY + n) * CC;
    float sq = 0.0f, dot = 0.0f;
    #pragma unroll
    for (int j = 0; j < CC / 32; ++j) {
        float v  = x[lane + 32 * j];
        float pv = pr[lane + 32 * j];
        sq  += v * v;
        dot += v * pv;
    }
    #pragma unroll
    for (int off = 16; off >= 1; off >>= 1) {
        sq  += __shfl_xor_sync(0xffffffffu, sq,  off);
        dot += __shfl_xor_sync(0xffffffffu, dot, off);
    }
    if (lane == 0)
        out[w] = 10.0f * dot / fmaxf(sqrtf(sq), 1e-12f);
}

// ===========================================================================
// Main: A-resident (256 x 384 bf16 in smem), B double-buffered cp.async
// stream. 512 threads = 16 warps (4 m-strips x 4 n-strips), warp tile 64x32.
// grid = (58, NWAY, BB).
// ===========================================================================
__device__ __forceinline__ void load_B_chunk(uint32_t Bdst,
                                             const __nv_bfloat16* bG,
                                             int g, int tid) {
    const int nt = g / NCH;
    const int ch = g - nt * NCH;
    #pragma unroll
    for (int v = 0; v < 2; ++v) {
        const int idx = tid + v * 512;        // 0..1023
        const int row = idx >> 3;
        const int seg = idx & 7;
        const int s   = nt * NTILE + row;
        const int sc  = (s < SS) ? s : 0;
        const void* src = bG + (size_t)sc * CC + ch * KCH + 8 * seg;
        const int sz = (s < SS) ? 16 : 0;
        cp16(Bdst + sw128((uint32_t)(row * 128 + seg * 16)), src, sz);
    }
}

__global__ void __launch_bounds__(512, 1)
mma_main_kernel(float* __restrict__ out) {
    extern __shared__ __align__(1024) char dsm[];

    const int tid  = threadIdx.x;
    const int warp = tid >> 5;
    const int lane = tid & 31;
    const int wy   = warp >> 2;      // 0..3: m strip of 64
    const int wx   = warp & 3;       // 0..3: n strip of 32
    const int gid  = lane >> 2;
    const int tig  = lane & 3;
    const int n     = blockIdx.y;
    const int b     = blockIdx.z;
    const int mrow0 = blockIdx.x * MC;

    const __nv_bfloat16* aG = g_fqb + (size_t)b * MROWS * CC;
    const __nv_bfloat16* bG = g_fsb + (size_t)(b * NWAY + n) * SS * CC;

    const uint32_t Abase = (uint32_t)__cvta_generic_to_shared(dsm);
    const uint32_t Bbase = Abase + B_OFFSET;

    // ---- prologue: A fully resident (6 chunks), B chunks 0 and 1 ----
    for (int v = tid; v < NCH * 2048; v += 512) {
        const int ch  = v >> 11;
        const int rem = v & 2047;
        const int row = rem >> 3;
        const int seg = rem & 7;
        const int gr  = mrow0 + row;
        const int grc = (gr < MROWS) ? gr : 0;
        const void* src = aG + (size_t)grc * CC + ch * KCH + 8 * seg;
        const int sz = (gr < MROWS) ? 16 : 0;
        cp16(Abase + ch * ACHUNK_BYTES + sw128((uint32_t)(row * 128 + seg * 16)),
             src, sz);
    }
    load_B_chunk(Bbase, bG, 0, tid);
    CP_COMMIT();                                   // group 0: A + B0
    load_B_chunk(Bbase + BCHUNK_BYTES, bG, 1, tid);
    CP_COMMIT();                                   // group 1: B1

    // per-thread ldmatrix address components
    const uint32_t xorv  = (uint32_t)((lane & 7) << 4);
    const uint32_t arow  = (uint32_t)((wy * 64 + (lane & 15)) * 128);
    const uint32_t brow  = (uint32_t)((wx * 32 + (lane & 7) + ((lane >> 4) << 3)) * 128);
    const uint32_t acolx = (uint32_t)(((lane >> 4) << 4));
    const uint32_t bcolx = (uint32_t)((((lane >> 3) & 1) << 4));

    float rmax[4][2];
    #pragma unroll
    for (int i = 0; i < 4; ++i) { rmax[i][0] = -1e30f; rmax[i][1] = -1e30f; }

    int g = 0;
    for (int nt = 0; nt < NST; ++nt) {
        float acc[4][4][4];
        #pragma unroll
        for (int i = 0; i < 4; ++i)
            #pragma unroll
            for (int j = 0; j < 4; ++j)
                #pragma unroll
                for (int r = 0; r < 4; ++r) acc[i][j][r] = 0.0f;

        for (int ch = 0; ch < NCH; ++ch, ++g) {
            CP_WAIT1();            // B chunk g (and A on first iteration) ready
            __syncthreads();

            const uint32_t Ach = Abase + ch * ACHUNK_BYTES;
            const uint32_t Bst = Bbase + (g & 1) * BCHUNK_BYTES;

            #pragma unroll
            for (int ks = 0; ks < 4; ++ks) {
                const uint32_t acol = ((uint32_t)(ks * 32) + acolx) ^ xorv;
                const uint32_t bcol = ((uint32_t)(ks * 32) + bcolx) ^ xorv;
                uint32_t a[4][4];
                #pragma unroll
                for (int i = 0; i < 4; ++i)
                    ldsm_x4(a[i][0], a[i][1], a[i][2], a[i][3],
                            Ach + arow + (uint32_t)(i * 2048) + acol);
                uint32_t bf[4][2];
                #pragma unroll
                for (int jp = 0; jp < 2; ++jp) {
                    uint32_t r0, r1, r2, r3;
                    ldsm_x4(r0, r1, r2, r3,
                            Bst + brow + (uint32_t)(jp * 2048) + bcol);
                    bf[2 * jp][0] = r0;     bf[2 * jp][1] = r1;
                    bf[2 * jp + 1][0] = r2; bf[2 * jp + 1][1] = r3;
                }
                #pragma unroll
                for (int i = 0; i < 4; ++i)
                    #pragma unroll
                    for (int j = 0; j < 4; ++j)
                        mma_bf16(acc[i][j][0], acc[i][j][1], acc[i][j][2], acc[i][j][3],
                                 a[i][0], a[i][1], a[i][2], a[i][3],
                                 bf[j][0], bf[j][1]);
            }
            __syncthreads();       // compute done before refilling this stage

            const int gn = g + 2;
            if (gn < NCHUNKS)
                load_B_chunk(Bbase + (gn & 1) * BCHUNK_BYTES, bG, gn, tid);
            CP_COMMIT();           // commit every iteration (may be empty)
        }

        // fold this s-tile into running per-row max (guard padded cols)
        #pragma unroll
        for (int i = 0; i < 4; ++i)
            #pragma unroll
            for (int j = 0; j < 4; ++j)
                #pragma unroll
                for (int r = 0; r < 4; ++r) {
                    const int col = nt * NTILE + wx * 32 + j * 8 + 2 * tig + (r & 1);
                    if (col < SS)
                        rmax[i][r >> 1] = fmaxf(rmax[i][r >> 1], acc[i][j][r]);
                }
    }

    // drain pipeline, then reuse B smem as the cross-warp max buffer
    CP_WAIT0();
    __syncthreads();
    float* red = (float*)(dsm + B_OFFSET);   // [256][4]

    #pragma unroll
    for (int i = 0; i < 4; ++i)
        #pragma unroll
        for (int h = 0; h < 2; ++h) {
            float v = rmax[i][h];
            v = fmaxf(v, __shfl_xor_sync(0xffffffffu, v, 1));
            v = fmaxf(v, __shfl_xor_sync(0xffffffffu, v, 2));
            rmax[i][h] = v;
        }
    if (tig == 0) {
        #pragma unroll
        for (int i = 0; i < 4; ++i)
            #pragma unroll
            for (int h = 0; h < 2; ++h)
                red[(wy * 64 + i * 16 + h * 8 + gid) * 4 + wx] = rmax[i][h];
    }
    __syncthreads();

    if (tid < MC) {
        const float m = fmaxf(fmaxf(red[tid * 4 + 0], red[tid * 4 + 1]),
                              fmaxf(red[tid * 4 + 2], red[tid * 4 + 3]));
        const int gr = mrow0 + tid;
        if (gr < MROWS) {
            const int q = gr / TT;
            atomicAdd(&out[(b * QQ + q) * NWAY + n], m * (1.0f / TT));
        }
    }
}

// ===========================================================================
// Launch. Inputs: feat_shot, feat_query, x_shot, x_query. Output: 1500 floats.
// ===========================================================================
extern "C" void kernel_launch(void* const* d_in, const int* in_sizes, int n_in,
                              void* d_out, int out_size) {
    const float* feat_shot  = (const float*)d_in[0];
    const float* feat_query = (const float*)d_in[1];
    const float* x_shot     = (const float*)d_in[2];
    const float* x_query    = (const float*)d_in[3];
    float* out = (float*)d_out;
    const int half = out_size / 2;   // 750

    static int attr_done = 0;
    if (!attr_done) {
        cudaFuncSetAttribute(mma_main_kernel,
                             cudaFuncAttributeMaxDynamicSharedMemorySize,
                             DSMEM_BYTES);
        attr_done = 1;
    }

    zero_kernel<<<(half + 255) / 256, 256>>>(out, half);

    {   // normalize + bf16 convert, warp per vector
        int warps  = VQ + VS;
        int blocks = (warps * 32 + 255) / 256;
        convert_kernel<<<blocks, 256>>>(feat_query, feat_shot);
    }

    proto_kernel<<<BB * NWAY, CC>>>(x_shot);

    {   // cls logits
        int warps  = BB * QQ * NWAY;
        int blocks = (warps * 32 + 255) / 256;
        cls_kernel<<<blocks, 256>>>(x_query, out + half);
    }

    dim3 grid((MROWS + MC - 1) / MC, NWAY, BB);   // (58, 5, 2)
    mma_main_kernel<<<grid, 512, DSMEM_BYTES>>>(out);
}